// round 1
// baseline (speedup 1.0000x reference)
#include <cuda_runtime.h>
#include <cuda_bf16.h>
#include <math.h>

#define BB 4
#define SS 1024
#define EE 512
#define HH 512
#define VV 32000
#define NHH 8
#define HD 64
#define EPSL 1e-5f

// ---------------- scratch (device globals; no allocation allowed) ----------------
__device__ float g_x[BB * SS * HH];          // embed out / LN out / proj out
__device__ float g_I[BB * SS * HH];          // GEMM out (liquid input current)
__device__ float g_act[BB * SS * HH];        // scan+tanh out
__device__ float g_qkv[BB * SS * 3 * HH];    // qkv
__device__ float g_o[BB * SS * HH];          // attention out

// ---------------- embed + positional encoding ----------------
__global__ void embed_pos_kernel(const int* __restrict__ tokens,
                                 const float* __restrict__ emb,
                                 float* __restrict__ x) {
    int idx = blockIdx.x * blockDim.x + threadIdx.x;
    if (idx >= BB * SS * EE) return;
    int e = idx & (EE - 1);
    int bs = idx / EE;
    int s = bs & (SS - 1);
    int tok = tokens[bs];
    int i2 = (e >> 1) << 1;                       // 2*(e/2)
    float div = expf(-(float)i2 * (9.210340371976184f / (float)EE)); // ln(10000)/E
    float arg = (float)s * div;
    float pe = (e & 1) ? cosf(arg) : sinf(arg);
    x[idx] = emb[(size_t)tok * EE + e] + pe;
}

// ---------------- generic SGEMM: C[M,N] = A[M,K] * W[N,K]^T + bias[N] ----------------
// M,N multiples of 128; K multiple of 16. 256 threads, 8x8 per thread.
__global__ __launch_bounds__(256) void sgemm_bias(
    const float* __restrict__ A, const float* __restrict__ W,
    const float* __restrict__ bias, float* __restrict__ C,
    int M, int N, int K) {
    __shared__ float As[16][128];
    __shared__ float Bs[16][128];
    const int tid = threadIdx.x;
    const int bm = blockIdx.y * 128;
    const int bn = blockIdx.x * 128;
    const int tx = tid & 15;
    const int ty = tid >> 4;

    float acc[8][8];
#pragma unroll
    for (int i = 0; i < 8; i++)
#pragma unroll
        for (int j = 0; j < 8; j++) acc[i][j] = 0.f;

    const float* Ab = A + (size_t)bm * K;
    const float* Wb = W + (size_t)bn * K;

    for (int kt = 0; kt < K; kt += 16) {
#pragma unroll
        for (int p = 0; p < 2; ++p) {
            int f = tid + 256 * p;
            int row = f >> 2;
            int c4 = (f & 3) * 4;
            float4 av = *(const float4*)(Ab + (size_t)row * K + kt + c4);
            float4 wv = *(const float4*)(Wb + (size_t)row * K + kt + c4);
            As[c4 + 0][row] = av.x; As[c4 + 1][row] = av.y;
            As[c4 + 2][row] = av.z; As[c4 + 3][row] = av.w;
            Bs[c4 + 0][row] = wv.x; Bs[c4 + 1][row] = wv.y;
            Bs[c4 + 2][row] = wv.z; Bs[c4 + 3][row] = wv.w;
        }
        __syncthreads();
#pragma unroll
        for (int k = 0; k < 16; ++k) {
            float a[8], b[8];
            *(float4*)&a[0] = *(const float4*)&As[k][ty * 8];
            *(float4*)&a[4] = *(const float4*)&As[k][ty * 8 + 4];
            *(float4*)&b[0] = *(const float4*)&Bs[k][tx * 8];
            *(float4*)&b[4] = *(const float4*)&Bs[k][tx * 8 + 4];
#pragma unroll
            for (int i = 0; i < 8; i++)
#pragma unroll
                for (int j = 0; j < 8; j++) acc[i][j] += a[i] * b[j];
        }
        __syncthreads();
    }
#pragma unroll
    for (int i = 0; i < 8; i++) {
        size_t rowg = (size_t)(bm + ty * 8 + i);
#pragma unroll
        for (int j = 0; j < 8; j += 4) {
            int col = bn + tx * 8 + j;
            float4 v;
            v.x = acc[i][j + 0] + bias[col + 0];
            v.y = acc[i][j + 1] + bias[col + 1];
            v.z = acc[i][j + 2] + bias[col + 2];
            v.w = acc[i][j + 3] + bias[col + 3];
            *(float4*)(C + rowg * N + col) = v;
        }
    }
}

// ---------------- liquid scan: double leaky integrator + tanh ----------------
// one thread per (b,h) chain; batched loads (8) to hide latency
__global__ void liquid_scan_kernel(const float* __restrict__ I,
                                   const float* __restrict__ tau,
                                   const float* __restrict__ log_dt,
                                   float* __restrict__ out) {
    int idx = blockIdx.x * blockDim.x + threadIdx.x;
    if (idx >= BB * HH) return;
    int b = idx / HH, h = idx & (HH - 1);
    float dt = expf(log_dt[0]);
    float a = dt / tau[h];
    float u = 0.f, s = 0.f;
    const float* Ip = I + (size_t)b * SS * HH + h;
    float* op = out + (size_t)b * SS * HH + h;
    for (int t = 0; t < SS; t += 8) {
        float It[8];
#pragma unroll
        for (int q = 0; q < 8; q++) It[q] = Ip[(size_t)(t + q) * HH];
#pragma unroll
        for (int q = 0; q < 8; q++) {
            float un = u + a * (It[q] - u);
            float sn = s + a * (u - s);      // uses OLD u (matches reference scan)
            u = un; s = sn;
            op[(size_t)(t + q) * HH] = tanhf(sn);
        }
    }
}

// ---------------- layernorm with affine ----------------
// one warp per row of H=512; 8 rows per 256-thread block
__global__ __launch_bounds__(256) void layernorm_kernel(
    const float* __restrict__ in, const float* __restrict__ g,
    const float* __restrict__ beta, float* __restrict__ out) {
    int row = blockIdx.x * 8 + (threadIdx.x >> 5);
    int lane = threadIdx.x & 31;
    const float* p = in + (size_t)row * HH;
    float sum = 0.f, sq = 0.f;
#pragma unroll
    for (int i = 0; i < HH / 32; i++) {
        float v = p[lane + i * 32];
        sum += v; sq += v * v;
    }
#pragma unroll
    for (int o = 16; o; o >>= 1) {
        sum += __shfl_xor_sync(0xffffffffu, sum, o);
        sq  += __shfl_xor_sync(0xffffffffu, sq, o);
    }
    float mu = sum * (1.0f / HH);
    float var = sq * (1.0f / HH) - mu * mu;
    float inv = rsqrtf(var + EPSL);
    float* q = out + (size_t)row * HH;
#pragma unroll
    for (int i = 0; i < HH / 32; i++) {
        int c = lane + i * 32;
        q[c] = g[c] * (p[c] - mu) * inv + beta[c];
    }
}

// ---------------- attention (flash-style, no mask) ----------------
// grid (S/32, NH, B); 128 threads; q-tile 32 rows, k-tile 64
__global__ __launch_bounds__(128) void attention_kernel(
    const float* __restrict__ qkv, float* __restrict__ o) {
    const int qt = blockIdx.x;
    const int h = blockIdx.y;
    const int b = blockIdx.z;
    __shared__ float Qs[32][HD + 1];
    __shared__ float Kst[HD][64];   // transposed: [d][j]
    __shared__ float Vs[64][HD];    // [j][d]
    const int tid = threadIdx.x;
    const int r = tid >> 2;
    const int part = tid & 3;
    const int lane = tid & 31;
    const size_t base = (size_t)b * SS * 3 * HH;

    for (int i = tid; i < 32 * 16; i += 128) {
        int row = i >> 4, d4 = (i & 15) * 4;
        float4 v = *(const float4*)(qkv + base + (size_t)(qt * 32 + row) * 3 * HH + h * HD + d4);
        Qs[row][d4 + 0] = v.x; Qs[row][d4 + 1] = v.y;
        Qs[row][d4 + 2] = v.z; Qs[row][d4 + 3] = v.w;
    }

    float acc[16];
#pragma unroll
    for (int i = 0; i < 16; i++) acc[i] = 0.f;
    float m = -1e30f, l = 0.f;

    for (int kt = 0; kt < SS; kt += 64) {
        __syncthreads();
        for (int i = tid; i < 64 * 16; i += 128) {
            int row = i >> 4, d4 = (i & 15) * 4;
            const float* kp = qkv + base + (size_t)(kt + row) * 3 * HH + HH + h * HD + d4;
            float4 kv = *(const float4*)kp;
            Kst[d4 + 0][row] = kv.x; Kst[d4 + 1][row] = kv.y;
            Kst[d4 + 2][row] = kv.z; Kst[d4 + 3][row] = kv.w;
            *(float4*)&Vs[row][d4] = *(const float4*)(kp + HH);
        }
        __syncthreads();

        float sc[16];
#pragma unroll
        for (int jj = 0; jj < 16; jj++) sc[jj] = 0.f;
        for (int d = 0; d < HD; ++d) {
            float qv = Qs[r][d];
            const float* kr = &Kst[d][part * 16];
#pragma unroll
            for (int jj = 0; jj < 16; jj++) sc[jj] += qv * kr[jj];
        }
        float tmax = -1e30f;
#pragma unroll
        for (int jj = 0; jj < 16; jj++) { sc[jj] *= 0.125f; tmax = fmaxf(tmax, sc[jj]); }
        tmax = fmaxf(tmax, __shfl_xor_sync(0xffffffffu, tmax, 1));
        tmax = fmaxf(tmax, __shfl_xor_sync(0xffffffffu, tmax, 2));
        float mnew = fmaxf(m, tmax);
        float corr = __expf(m - mnew);
        float pl[16];
        float psum = 0.f;
#pragma unroll
        for (int jj = 0; jj < 16; jj++) { pl[jj] = __expf(sc[jj] - mnew); psum += pl[jj]; }
        psum += __shfl_xor_sync(0xffffffffu, psum, 1);
        psum += __shfl_xor_sync(0xffffffffu, psum, 2);
        l = l * corr + psum;
        m = mnew;
#pragma unroll
        for (int i = 0; i < 16; i++) acc[i] *= corr;
#pragma unroll
        for (int src = 0; src < 4; ++src) {
#pragma unroll
            for (int jj = 0; jj < 16; jj++) {
                float p = __shfl_sync(0xffffffffu, pl[jj], (lane & ~3) | src);
                const float* vr = &Vs[src * 16 + jj][part * 16];
#pragma unroll
                for (int dd = 0; dd < 16; dd++) acc[dd] += p * vr[dd];
            }
        }
    }
    float linv = 1.f / l;
    float* op = o + (size_t)(b * SS + qt * 32 + r) * HH + h * HD + part * 16;
#pragma unroll
    for (int dd = 0; dd < 16; dd++) op[dd] = acc[dd] * linv;
}

// ---------------- launch ----------------
extern "C" void kernel_launch(void* const* d_in, const int* in_sizes, int n_in,
                              void* d_out, int out_size) {
    const int*   tokens = (const int*)d_in[0];
    const float* emb    = (const float*)d_in[1];
    const float* W0     = (const float*)d_in[2];
    const float* b0     = (const float*)d_in[3];
    const float* tau0   = (const float*)d_in[4];
    const float* g0     = (const float*)d_in[5];
    const float* be0    = (const float*)d_in[6];
    const float* W1     = (const float*)d_in[7];
    const float* b1     = (const float*)d_in[8];
    const float* tau1   = (const float*)d_in[9];
    const float* g1     = (const float*)d_in[10];
    const float* be1    = (const float*)d_in[11];
    const float* w_in   = (const float*)d_in[12];
    const float* b_in   = (const float*)d_in[13];
    const float* w_o    = (const float*)d_in[14];
    const float* b_o    = (const float*)d_in[15];
    const float* Wout   = (const float*)d_in[16];
    const float* bout   = (const float*)d_in[17];
    const float* log_dt = (const float*)d_in[18];
    float* out = (float*)d_out;

    float *px, *pI, *pact, *pqkv, *po;
    cudaGetSymbolAddress((void**)&px,   g_x);
    cudaGetSymbolAddress((void**)&pI,   g_I);
    cudaGetSymbolAddress((void**)&pact, g_act);
    cudaGetSymbolAddress((void**)&pqkv, g_qkv);
    cudaGetSymbolAddress((void**)&po,   g_o);

    const int M = BB * SS;  // 4096

    // 1. embed + pos
    embed_pos_kernel<<<(BB * SS * EE) / 256, 256>>>(tokens, emb, px);

    // 2. liquid layer 0
    sgemm_bias<<<dim3(HH / 128, M / 128), 256>>>(px, W0, b0, pI, M, HH, EE);
    liquid_scan_kernel<<<(BB * HH + 255) / 256, 256>>>(pI, tau0, log_dt, pact);
    layernorm_kernel<<<M / 8, 256>>>(pact, g0, be0, px);

    // 3. liquid layer 1
    sgemm_bias<<<dim3(HH / 128, M / 128), 256>>>(px, W1, b1, pI, M, HH, HH);
    liquid_scan_kernel<<<(BB * HH + 255) / 256, 256>>>(pI, tau1, log_dt, pact);
    layernorm_kernel<<<M / 8, 256>>>(pact, g1, be1, px);

    // 4. MHA
    sgemm_bias<<<dim3(3 * HH / 128, M / 128), 256>>>(px, w_in, b_in, pqkv, M, 3 * HH, HH);
    attention_kernel<<<dim3(SS / 32, NHH, BB), 128>>>(pqkv, po);
    sgemm_bias<<<dim3(HH / 128, M / 128), 256>>>(po, w_o, b_o, px, M, HH, HH);

    // 5. vocab projection
    sgemm_bias<<<dim3(VV / 128, M / 128), 256>>>(px, Wout, bout, out, M, VV, HH);
}

// round 2
// speedup vs baseline: 1.6933x; 1.6933x over previous
#include <cuda_runtime.h>
#include <cuda_bf16.h>
#include <math.h>
#include <stdint.h>

#define BB 4
#define SS 1024
#define EE 512
#define HH 512
#define VV 32000
#define NHH 8
#define HD 64
#define EPSL 1e-5f

// ---------------- scratch (device globals; no allocation allowed) ----------------
__device__ float g_x[BB * SS * HH];
__device__ float g_I[BB * SS * HH];
__device__ float g_act[BB * SS * HH];
__device__ float g_qkv[BB * SS * 3 * HH];
__device__ float g_o[BB * SS * HH];

// ---------------- embed + positional encoding ----------------
__global__ void embed_pos_kernel(const int* __restrict__ tokens,
                                 const float* __restrict__ emb,
                                 float* __restrict__ x) {
    int idx = blockIdx.x * blockDim.x + threadIdx.x;
    if (idx >= BB * SS * EE) return;
    int e = idx & (EE - 1);
    int bs = idx / EE;
    int s = bs & (SS - 1);
    int tok = tokens[bs];
    int i2 = (e >> 1) << 1;
    float div = expf(-(float)i2 * (9.210340371976184f / (float)EE));
    float arg = (float)s * div;
    float pe = (e & 1) ? cosf(arg) : sinf(arg);
    x[idx] = emb[(size_t)tok * EE + e] + pe;
}

// ---------------- tf32 tensor-core GEMM ----------------
// C[M,N] = A[M,K] * W[N,K]^T + bias[N]
// block tile 128x128, BK=32, 256 threads (8 warps), warp tile 64x32
__device__ __forceinline__ uint32_t f2tf32(float x) {
    uint32_t r;
    asm("cvt.rna.tf32.f32 %0, %1;" : "=r"(r) : "f"(x));
    return r;
}

__global__ __launch_bounds__(256) void gemm_tf32(
    const float* __restrict__ A, const float* __restrict__ W,
    const float* __restrict__ bias, float* __restrict__ C,
    int M, int N, int K) {
    __shared__ uint32_t As[4096];   // fragment-ordered A tile  (16KB)
    __shared__ uint32_t Bs[4096];   // fragment-ordered B tile  (16KB)

    const int tid = threadIdx.x;
    const int lane = tid & 31;
    const int wid = tid >> 5;
    const int warp_m = wid & 1;        // 0..1  (64 rows each)
    const int warp_n = wid >> 1;       // 0..3  (32 cols each)
    const int bm = blockIdx.y * 128;
    const int bn = blockIdx.x * 128;

    float c[4][4][4];
#pragma unroll
    for (int mt = 0; mt < 4; mt++)
#pragma unroll
        for (int nt = 0; nt < 4; nt++)
#pragma unroll
            for (int q = 0; q < 4; q++) c[mt][nt][q] = 0.f;

    const int arow = tid >> 3;          // 0..31
    const int acol = (tid & 7) * 4;     // 0..28 (k within chunk)

    // precompute smem scatter bases (independent of chunk)
    int a_addr[4], b_addr[4];
#pragma unroll
    for (int p = 0; p < 4; p++) {
        int grow = arow + p * 32;       // row within 128 tile
        int r = grow & 15;
        int m16 = grow >> 4;
        int tileA = (acol >> 3) * 8 + m16;
        a_addr[p] = tileA * 128 + ((r & 7) * 4) * 4 + ((r >> 3) + 2 * ((acol >> 2) & 1));
        int rn = grow & 7;
        int n8 = grow >> 3;
        int tileB = (acol >> 3) * 16 + n8;
        b_addr[p] = tileB * 64 + (rn * 4) * 2 + ((acol >> 2) & 1);
    }

    const int nchunk = K >> 5;
    for (int kc = 0; kc < nchunk; ++kc) {
        float4 av[4], wv[4];
#pragma unroll
        for (int p = 0; p < 4; p++) {
            av[p] = *(const float4*)(A + (size_t)(bm + arow + p * 32) * K + kc * 32 + acol);
            wv[p] = *(const float4*)(W + (size_t)(bn + arow + p * 32) * K + kc * 32 + acol);
        }
        __syncthreads();   // previous chunk's compute done
#pragma unroll
        for (int p = 0; p < 4; p++) {
            As[a_addr[p] + 0] = f2tf32(av[p].x);
            As[a_addr[p] + 4] = f2tf32(av[p].y);
            As[a_addr[p] + 8] = f2tf32(av[p].z);
            As[a_addr[p] + 12] = f2tf32(av[p].w);
            Bs[b_addr[p] + 0] = f2tf32(wv[p].x);
            Bs[b_addr[p] + 2] = f2tf32(wv[p].y);
            Bs[b_addr[p] + 4] = f2tf32(wv[p].z);
            Bs[b_addr[p] + 6] = f2tf32(wv[p].w);
        }
        __syncthreads();

#pragma unroll
        for (int kk = 0; kk < 4; kk++) {
            uint4 af[4];
            uint2 bf[4];
#pragma unroll
            for (int mt = 0; mt < 4; mt++)
                af[mt] = *(const uint4*)&As[(kk * 8 + warp_m * 4 + mt) * 128 + lane * 4];
#pragma unroll
            for (int nt = 0; nt < 4; nt++)
                bf[nt] = *(const uint2*)&Bs[(kk * 16 + warp_n * 4 + nt) * 64 + lane * 2];
#pragma unroll
            for (int mt = 0; mt < 4; mt++)
#pragma unroll
                for (int nt = 0; nt < 4; nt++) {
                    asm volatile(
                        "mma.sync.aligned.m16n8k8.row.col.f32.tf32.tf32.f32 "
                        "{%0,%1,%2,%3}, {%4,%5,%6,%7}, {%8,%9}, {%0,%1,%2,%3};"
                        : "+f"(c[mt][nt][0]), "+f"(c[mt][nt][1]),
                          "+f"(c[mt][nt][2]), "+f"(c[mt][nt][3])
                        : "r"(af[mt].x), "r"(af[mt].y), "r"(af[mt].z), "r"(af[mt].w),
                          "r"(bf[nt].x), "r"(bf[nt].y));
                }
        }
    }

    // epilogue
    const int g = lane >> 2;
    const int t4 = lane & 3;
#pragma unroll
    for (int mt = 0; mt < 4; mt++) {
        int row0 = bm + warp_m * 64 + mt * 16 + g;
#pragma unroll
        for (int nt = 0; nt < 4; nt++) {
            int col = bn + warp_n * 32 + nt * 8 + t4 * 2;
            float b0 = bias[col], b1 = bias[col + 1];
            float2 v0 = make_float2(c[mt][nt][0] + b0, c[mt][nt][1] + b1);
            float2 v1 = make_float2(c[mt][nt][2] + b0, c[mt][nt][3] + b1);
            *(float2*)(C + (size_t)row0 * N + col) = v0;
            *(float2*)(C + (size_t)(row0 + 8) * N + col) = v1;
        }
    }
}

// ---------------- liquid scan ----------------
__global__ void liquid_scan_kernel(const float* __restrict__ I,
                                   const float* __restrict__ tau,
                                   const float* __restrict__ log_dt,
                                   float* __restrict__ out) {
    int idx = blockIdx.x * blockDim.x + threadIdx.x;
    if (idx >= BB * HH) return;
    int b = idx / HH, h = idx & (HH - 1);
    float dt = expf(log_dt[0]);
    float a = dt / tau[h];
    float u = 0.f, s = 0.f;
    const float* Ip = I + (size_t)b * SS * HH + h;
    float* op = out + (size_t)b * SS * HH + h;
    for (int t = 0; t < SS; t += 8) {
        float It[8];
#pragma unroll
        for (int q = 0; q < 8; q++) It[q] = Ip[(size_t)(t + q) * HH];
#pragma unroll
        for (int q = 0; q < 8; q++) {
            float un = u + a * (It[q] - u);
            float sn = s + a * (u - s);
            u = un; s = sn;
            op[(size_t)(t + q) * HH] = tanhf(sn);
        }
    }
}

// ---------------- layernorm ----------------
__global__ __launch_bounds__(256) void layernorm_kernel(
    const float* __restrict__ in, const float* __restrict__ g,
    const float* __restrict__ beta, float* __restrict__ out) {
    int row = blockIdx.x * 8 + (threadIdx.x >> 5);
    int lane = threadIdx.x & 31;
    const float* p = in + (size_t)row * HH;
    float sum = 0.f, sq = 0.f;
#pragma unroll
    for (int i = 0; i < HH / 32; i++) {
        float v = p[lane + i * 32];
        sum += v; sq += v * v;
    }
#pragma unroll
    for (int o = 16; o; o >>= 1) {
        sum += __shfl_xor_sync(0xffffffffu, sum, o);
        sq  += __shfl_xor_sync(0xffffffffu, sq, o);
    }
    float mu = sum * (1.0f / HH);
    float var = sq * (1.0f / HH) - mu * mu;
    float inv = rsqrtf(var + EPSL);
    float* q = out + (size_t)row * HH;
#pragma unroll
    for (int i = 0; i < HH / 32; i++) {
        int c = lane + i * 32;
        q[c] = g[c] * (p[c] - mu) * inv + beta[c];
    }
}

// ---------------- attention (flash-style) ----------------
__global__ __launch_bounds__(128) void attention_kernel(
    const float* __restrict__ qkv, float* __restrict__ o) {
    const int qt = blockIdx.x;
    const int h = blockIdx.y;
    const int b = blockIdx.z;
    __shared__ float Qs[32][HD + 1];
    __shared__ float Kst[HD][64];
    __shared__ float Vs[64][HD];
    const int tid = threadIdx.x;
    const int r = tid >> 2;
    const int part = tid & 3;
    const int lane = tid & 31;
    const size_t base = (size_t)b * SS * 3 * HH;

    for (int i = tid; i < 32 * 16; i += 128) {
        int row = i >> 4, d4 = (i & 15) * 4;
        float4 v = *(const float4*)(qkv + base + (size_t)(qt * 32 + row) * 3 * HH + h * HD + d4);
        Qs[row][d4 + 0] = v.x; Qs[row][d4 + 1] = v.y;
        Qs[row][d4 + 2] = v.z; Qs[row][d4 + 3] = v.w;
    }

    float acc[16];
#pragma unroll
    for (int i = 0; i < 16; i++) acc[i] = 0.f;
    float m = -1e30f, l = 0.f;

    for (int kt = 0; kt < SS; kt += 64) {
        __syncthreads();
        for (int i = tid; i < 64 * 16; i += 128) {
            int row = i >> 4, d4 = (i & 15) * 4;
            const float* kp = qkv + base + (size_t)(kt + row) * 3 * HH + HH + h * HD + d4;
            float4 kv = *(const float4*)kp;
            Kst[d4 + 0][row] = kv.x; Kst[d4 + 1][row] = kv.y;
            Kst[d4 + 2][row] = kv.z; Kst[d4 + 3][row] = kv.w;
            *(float4*)&Vs[row][d4] = *(const float4*)(kp + HH);
        }
        __syncthreads();

        float sc[16];
#pragma unroll
        for (int jj = 0; jj < 16; jj++) sc[jj] = 0.f;
        for (int d = 0; d < HD; ++d) {
            float qv = Qs[r][d];
            const float* kr = &Kst[d][part * 16];
#pragma unroll
            for (int jj = 0; jj < 16; jj++) sc[jj] += qv * kr[jj];
        }
        float tmax = -1e30f;
#pragma unroll
        for (int jj = 0; jj < 16; jj++) { sc[jj] *= 0.125f; tmax = fmaxf(tmax, sc[jj]); }
        tmax = fmaxf(tmax, __shfl_xor_sync(0xffffffffu, tmax, 1));
        tmax = fmaxf(tmax, __shfl_xor_sync(0xffffffffu, tmax, 2));
        float mnew = fmaxf(m, tmax);
        float corr = __expf(m - mnew);
        float pl[16];
        float psum = 0.f;
#pragma unroll
        for (int jj = 0; jj < 16; jj++) { pl[jj] = __expf(sc[jj] - mnew); psum += pl[jj]; }
        psum += __shfl_xor_sync(0xffffffffu, psum, 1);
        psum += __shfl_xor_sync(0xffffffffu, psum, 2);
        l = l * corr + psum;
        m = mnew;
#pragma unroll
        for (int i = 0; i < 16; i++) acc[i] *= corr;
#pragma unroll
        for (int src = 0; src < 4; ++src) {
#pragma unroll
            for (int jj = 0; jj < 16; jj++) {
                float p = __shfl_sync(0xffffffffu, pl[jj], (lane & ~3) | src);
                const float* vr = &Vs[src * 16 + jj][part * 16];
#pragma unroll
                for (int dd = 0; dd < 16; dd++) acc[dd] += p * vr[dd];
            }
        }
    }
    float linv = 1.f / l;
    float* op = o + (size_t)(b * SS + qt * 32 + r) * HH + h * HD + part * 16;
#pragma unroll
    for (int dd = 0; dd < 16; dd++) op[dd] = acc[dd] * linv;
}

// ---------------- launch ----------------
extern "C" void kernel_launch(void* const* d_in, const int* in_sizes, int n_in,
                              void* d_out, int out_size) {
    const int*   tokens = (const int*)d_in[0];
    const float* emb    = (const float*)d_in[1];
    const float* W0     = (const float*)d_in[2];
    const float* b0     = (const float*)d_in[3];
    const float* tau0   = (const float*)d_in[4];
    const float* g0     = (const float*)d_in[5];
    const float* be0    = (const float*)d_in[6];
    const float* W1     = (const float*)d_in[7];
    const float* b1     = (const float*)d_in[8];
    const float* tau1   = (const float*)d_in[9];
    const float* g1     = (const float*)d_in[10];
    const float* be1    = (const float*)d_in[11];
    const float* w_in   = (const float*)d_in[12];
    const float* b_in   = (const float*)d_in[13];
    const float* w_o    = (const float*)d_in[14];
    const float* b_o    = (const float*)d_in[15];
    const float* Wout   = (const float*)d_in[16];
    const float* bout   = (const float*)d_in[17];
    const float* log_dt = (const float*)d_in[18];
    float* out = (float*)d_out;

    float *px, *pI, *pact, *pqkv, *po;
    cudaGetSymbolAddress((void**)&px,   g_x);
    cudaGetSymbolAddress((void**)&pI,   g_I);
    cudaGetSymbolAddress((void**)&pact, g_act);
    cudaGetSymbolAddress((void**)&pqkv, g_qkv);
    cudaGetSymbolAddress((void**)&po,   g_o);

    const int M = BB * SS;  // 4096

    embed_pos_kernel<<<(BB * SS * EE) / 256, 256>>>(tokens, emb, px);

    gemm_tf32<<<dim3(HH / 128, M / 128), 256>>>(px, W0, b0, pI, M, HH, EE);
    liquid_scan_kernel<<<(BB * HH + 255) / 256, 256>>>(pI, tau0, log_dt, pact);
    layernorm_kernel<<<M / 8, 256>>>(pact, g0, be0, px);

    gemm_tf32<<<dim3(HH / 128, M / 128), 256>>>(px, W1, b1, pI, M, HH, HH);
    liquid_scan_kernel<<<(BB * HH + 255) / 256, 256>>>(pI, tau1, log_dt, pact);
    layernorm_kernel<<<M / 8, 256>>>(pact, g1, be1, px);

    gemm_tf32<<<dim3(3 * HH / 128, M / 128), 256>>>(px, w_in, b_in, pqkv, M, 3 * HH, HH);
    attention_kernel<<<dim3(SS / 32, NHH, BB), 128>>>(pqkv, po);
    gemm_tf32<<<dim3(HH / 128, M / 128), 256>>>(po, w_o, b_o, px, M, HH, HH);

    gemm_tf32<<<dim3(VV / 128, M / 128), 256>>>(px, Wout, bout, out, M, VV, HH);
}